// round 9
// baseline (speedup 1.0000x reference)
#include <cuda_runtime.h>
#include <cuda_fp16.h>
#include <math.h>
#include <stdint.h>

#define NN 50000
#define NE 800000
#define DHID 128
#define NH 4
#define DHEAD 32
#define OUTD 512
#define NEG_SLOPE 0.2f
#define EPSV 1e-9f

// GEMM smem layout (floats): 3 stages A[64][20] + 3 stages B[16][132]
#define A_STRIDE 20
#define B_STRIDE 132
#define A_STAGE (64 * A_STRIDE)           // 1280
#define B_STAGE (16 * B_STRIDE)           // 2112
#define SMEM_FLOATS (3 * A_STAGE + 3 * B_STAGE)
#define SMEM_BYTES (SMEM_FLOATS * 4)      // 40704

// ---------------- scratch (device globals; no allocation) ----------------
__device__ __half g_Whh[NN * DHID];   // fp16 message payload
__device__ float g_z[NN * DHID];
__device__ float g_el[NN * NH];
__device__ float g_er[NN * NH];
__device__ float g_z2[NN * DHEAD];
__device__ int   g_cnt[NN];
__device__ int   g_rowptr[NN + 1];
__device__ int   g_fill[NN];
__device__ int   g_csrc[NE];

__device__ __forceinline__ float lrelu(float x) {
    return x > 0.0f ? x : NEG_SLOPE * x;
}

__device__ __forceinline__ uint32_t f2tf32(float x) {
    uint32_t u;
    asm("cvt.rna.tf32.f32 %0, %1;" : "=r"(u) : "f"(x));
    return u;
}

__device__ __forceinline__ void mma_tf32(float* c, const uint32_t* a, const uint32_t* b) {
    asm volatile(
        "mma.sync.aligned.m16n8k8.row.col.f32.tf32.tf32.f32 "
        "{%0,%1,%2,%3}, {%4,%5,%6,%7}, {%8,%9}, {%0,%1,%2,%3};"
        : "+f"(c[0]), "+f"(c[1]), "+f"(c[2]), "+f"(c[3])
        : "r"(a[0]), "r"(a[1]), "r"(a[2]), "r"(a[3]), "r"(b[0]), "r"(b[1]));
}

__device__ __forceinline__ uint32_t su(const void* p) {
    return (uint32_t)__cvta_generic_to_shared(p);
}

__device__ __forceinline__ void cp16(uint32_t dst, const void* src, bool p) {
    int sz = p ? 16 : 0;
    asm volatile("cp.async.cg.shared.global [%0], [%1], 16, %2;"
                 :: "r"(dst), "l"(src), "r"(sz));
}

// ================= tensor-core GEMM (tf32 mma.sync) =================
// Block tile 64x128, 8 warps (2m x 4n) of 32x32 warp tiles, 3-stage cp.async.
// FUSE=1: writes fp16 g_Whh + g_el/g_er (grid.x must be 1, N==128); no fp32 C.
// FUSE=0: writes fp32 C (+bias).  Requires K % 16 == 0, K >= 32, N % 128 == 0.
template <int FUSE>
__global__ void __launch_bounds__(256, 3)
gemm_tc(const float* __restrict__ A, const float* __restrict__ B,
        const float* __restrict__ bias, float* __restrict__ C,
        int M, int N, int K,
        const float* __restrict__ al, const float* __restrict__ ar) {
    extern __shared__ float smem[];

    const int tid = threadIdx.x;
    const int wid = tid >> 5, lane = tid & 31;
    const int g = lane >> 2, t = lane & 3;
    const int wm = wid & 1;               // 2 warp rows x 32
    const int wn = wid >> 1;              // 4 warp cols x 32
    const int rowBase = blockIdx.y * 64;
    const int colBase = blockIdx.x * 128;

    const int aRow = tid >> 2, aK0 = (tid & 3) * 4;
    const int bK0 = tid >> 5, bN0 = (tid & 31) * 4;
    const bool ap = (rowBase + aRow) < M;
    const float* aSrc = A + (size_t)(ap ? rowBase + aRow : 0) * K + aK0;
    const float* bSrc0 = B + (size_t)bK0 * N + colBase + bN0;
    const float* bSrc1 = B + (size_t)(bK0 + 8) * N + colBase + bN0;

    float acc[2][4][4];
#pragma unroll
    for (int mf = 0; mf < 2; mf++)
#pragma unroll
        for (int nf = 0; nf < 4; nf++)
#pragma unroll
            for (int r = 0; r < 4; r++) acc[mf][nf][r] = 0.0f;

    const int nStages = K >> 4;

    uint32_t aDst = su(smem + aRow * A_STRIDE + aK0);
    uint32_t bDst0 = su(smem + 3 * A_STAGE + bK0 * B_STRIDE + bN0);
    uint32_t bDst1 = su(smem + 3 * A_STAGE + (bK0 + 8) * B_STRIDE + bN0);

#pragma unroll
    for (int s = 0; s < 2; s++) {
        int k0g = s * 16;
        cp16(aDst + s * A_STAGE * 4, aSrc + k0g, ap);
        cp16(bDst0 + s * B_STAGE * 4, bSrc0 + (size_t)k0g * N, true);
        cp16(bDst1 + s * B_STAGE * 4, bSrc1 + (size_t)k0g * N, true);
        asm volatile("cp.async.commit_group;");
    }

    for (int st = 0; st < nStages; st++) {
        if (nStages - st >= 2) asm volatile("cp.async.wait_group 1;" ::: "memory");
        else                   asm volatile("cp.async.wait_group 0;" ::: "memory");
        __syncthreads();

        const int cur = st % 3;
        const float* Asf = smem + cur * A_STAGE;
        const float* Bsf = smem + 3 * A_STAGE + cur * B_STAGE;

#pragma unroll
        for (int kk = 0; kk < 2; kk++) {
            const int k0 = kk * 8;
            uint32_t af[2][4], bf[4][2];
#pragma unroll
            for (int mf = 0; mf < 2; mf++) {
                int r0 = wm * 32 + mf * 16 + g;
                af[mf][0] = f2tf32(Asf[r0 * A_STRIDE + k0 + t]);
                af[mf][1] = f2tf32(Asf[(r0 + 8) * A_STRIDE + k0 + t]);
                af[mf][2] = f2tf32(Asf[r0 * A_STRIDE + k0 + t + 4]);
                af[mf][3] = f2tf32(Asf[(r0 + 8) * A_STRIDE + k0 + t + 4]);
            }
#pragma unroll
            for (int nf = 0; nf < 4; nf++) {
                int n0 = wn * 32 + nf * 8 + g;
                bf[nf][0] = f2tf32(Bsf[(k0 + t) * B_STRIDE + n0]);
                bf[nf][1] = f2tf32(Bsf[(k0 + t + 4) * B_STRIDE + n0]);
            }
#pragma unroll
            for (int mf = 0; mf < 2; mf++)
#pragma unroll
                for (int nf = 0; nf < 4; nf++)
                    mma_tf32(acc[mf][nf], af[mf], bf[nf]);
        }

        if (st + 2 < nStages) {
            int s = (st + 2) % 3;
            int k0g = (st + 2) * 16;
            cp16(aDst + s * A_STAGE * 4, aSrc + k0g, ap);
            cp16(bDst0 + s * B_STAGE * 4, bSrc0 + (size_t)k0g * N, true);
            cp16(bDst1 + s * B_STAGE * 4, bSrc1 + (size_t)k0g * N, true);
            asm volatile("cp.async.commit_group;");
        }
    }

    if (!FUSE) {
#pragma unroll
        for (int mf = 0; mf < 2; mf++) {
            int row0 = rowBase + wm * 32 + mf * 16 + g;
#pragma unroll
            for (int nf = 0; nf < 4; nf++) {
                int col = colBase + wn * 32 + nf * 8 + 2 * t;
                float b0 = bias ? bias[col] : 0.f;
                float b1 = bias ? bias[col + 1] : 0.f;
                if (row0 < M) {
                    float2 v = make_float2(acc[mf][nf][0] + b0, acc[mf][nf][1] + b1);
                    *(float2*)(C + (size_t)row0 * N + col) = v;
                }
                if (row0 + 8 < M) {
                    float2 v = make_float2(acc[mf][nf][2] + b0, acc[mf][nf][3] + b1);
                    *(float2*)(C + (size_t)(row0 + 8) * N + col) = v;
                }
            }
        }
    } else {
        float elp[2][2] = {}, erp[2][2] = {};   // [mf][rh]
#pragma unroll
        for (int nf = 0; nf < 4; nf++) {
            int col = wn * 32 + nf * 8 + 2 * t;
            float la0 = al[col], la1 = al[col + 1];
            float ra0 = ar[col], ra1 = ar[col + 1];
#pragma unroll
            for (int mf = 0; mf < 2; mf++) {
                elp[mf][0] += acc[mf][nf][0] * la0 + acc[mf][nf][1] * la1;
                elp[mf][1] += acc[mf][nf][2] * la0 + acc[mf][nf][3] * la1;
                erp[mf][0] += acc[mf][nf][0] * ra0 + acc[mf][nf][1] * ra1;
                erp[mf][1] += acc[mf][nf][2] * ra0 + acc[mf][nf][3] * ra1;
                int row0 = rowBase + wm * 32 + mf * 16 + g;
                if (row0 < M) {
                    __half2 hv = __floats2half2_rn(acc[mf][nf][0], acc[mf][nf][1]);
                    *(__half2*)(g_Whh + (size_t)row0 * DHID + col) = hv;
                }
                if (row0 + 8 < M) {
                    __half2 hv = __floats2half2_rn(acc[mf][nf][2], acc[mf][nf][3]);
                    *(__half2*)(g_Whh + (size_t)(row0 + 8) * DHID + col) = hv;
                }
            }
        }
#pragma unroll
        for (int mf = 0; mf < 2; mf++)
#pragma unroll
            for (int rh = 0; rh < 2; rh++) {
                float v = elp[mf][rh];
                v += __shfl_xor_sync(0xFFFFFFFFu, v, 1);
                v += __shfl_xor_sync(0xFFFFFFFFu, v, 2);
                elp[mf][rh] = v;
                float w = erp[mf][rh];
                w += __shfl_xor_sync(0xFFFFFFFFu, w, 1);
                w += __shfl_xor_sync(0xFFFFFFFFu, w, 2);
                erp[mf][rh] = w;
            }
        if (t == 0) {
#pragma unroll
            for (int mf = 0; mf < 2; mf++)
#pragma unroll
                for (int rh = 0; rh < 2; rh++) {
                    int gr = rowBase + wm * 32 + mf * 16 + g + rh * 8;
                    if (gr < M) {
                        g_el[gr * NH + wn] = elp[mf][rh];
                        g_er[gr * NH + wn] = erp[mf][rh];
                    }
                }
        }
    }
}

// ---------------- streams/events for fork-join + func attrs ----------------
static cudaStream_t g_s2;
static cudaEvent_t g_evFork, g_evCsr;
struct HostInit {
    HostInit() {
        cudaStreamCreateWithFlags(&g_s2, cudaStreamNonBlocking);
        cudaEventCreateWithFlags(&g_evFork, cudaEventDisableTiming);
        cudaEventCreateWithFlags(&g_evCsr, cudaEventDisableTiming);
        cudaFuncSetAttribute(gemm_tc<0>, cudaFuncAttributeMaxDynamicSharedMemorySize, SMEM_BYTES);
        cudaFuncSetAttribute(gemm_tc<1>, cudaFuncAttributeMaxDynamicSharedMemorySize, SMEM_BYTES);
    }
};
static HostInit g_hostInit;

// ================= CSR build (int4-vectorized, no epos array) =================
__global__ void k_count(const int4* __restrict__ dst4) {
    int i = blockIdx.x * blockDim.x + threadIdx.x;
    if (i >= NE / 4) return;
    int4 d = dst4[i];
    atomicAdd(&g_cnt[d.x], 1);
    atomicAdd(&g_cnt[d.y], 1);
    atomicAdd(&g_cnt[d.z], 1);
    atomicAdd(&g_cnt[d.w], 1);
}

__global__ void k_scan() {
    __shared__ int warpsum[32];
    const int T = 1024;
    const int CH = (NN + T - 1) / T;
    int t = threadIdx.x;
    int lane = t & 31, wid = t >> 5;
    int lo = t * CH;
    int hi = lo + CH; if (hi > NN) hi = NN;
    if (lo > NN) lo = NN;
    int s = 0;
    for (int i = lo; i < hi; i++) s += g_cnt[i];
    int v = s;
#pragma unroll
    for (int o = 1; o < 32; o <<= 1) {
        int u = __shfl_up_sync(0xFFFFFFFFu, v, o);
        if (lane >= o) v += u;
    }
    if (lane == 31) warpsum[wid] = v;
    __syncthreads();
    if (wid == 0) {
        int w = warpsum[lane];
#pragma unroll
        for (int o = 1; o < 32; o <<= 1) {
            int u = __shfl_up_sync(0xFFFFFFFFu, w, o);
            if (lane >= o) w += u;
        }
        warpsum[lane] = w;
    }
    __syncthreads();
    int excl = v - s + (wid > 0 ? warpsum[wid - 1] : 0);
    int run = excl;
    for (int i = lo; i < hi; i++) {
        g_rowptr[i] = run;
        g_fill[i] = run;
        run += g_cnt[i];
    }
    if (t == T - 1) g_rowptr[NN] = run;
}

__global__ void k_fill(const int4* __restrict__ src4, const int4* __restrict__ dst4) {
    int i = blockIdx.x * blockDim.x + threadIdx.x;
    if (i >= NE / 4) return;
    int4 s = src4[i];
    int4 d = dst4[i];
    g_csrc[atomicAdd(&g_fill[d.x], 1)] = s.x;
    g_csrc[atomicAdd(&g_fill[d.y], 1)] = s.y;
    g_csrc[atomicAdd(&g_fill[d.z], 1)] = s.z;
    g_csrc[atomicAdd(&g_fill[d.w], 1)] = s.w;
}

// ====== fused softmax + aggregate: warp per node, half-warp edge pairing ======
// Lanes 0-15 process even edges, 16-31 odd edges; each lane owns 8 dims (uint4).
template <int LAYER>
__global__ void k_gat_agg(const float* __restrict__ bias) {
    __shared__ float exsAll[8][128];
    const int wIn = threadIdx.x >> 5;
    const int n = (blockIdx.x << 3) + wIn;
    if (n >= NN) return;
    float* exsw = exsAll[wIn];
    const int lane = threadIdx.x & 31;
    const int hw = lane >> 4;            // 0: even edges, 1: odd edges
    const int l16 = lane & 15;
    const int myh8 = l16 >> 2;           // head owned by this lane's 8 dims
    const int dimBase = l16 * 8;

    int beg = g_rowptr[n], end = g_rowptr[n + 1];
    float4 er4 = *(const float4*)(g_er + n * NH);

    float a0 = 0.f, a1 = 0.f, a2 = 0.f, a3 = 0.f;
    float a4 = 0.f, a5 = 0.f, a6 = 0.f, a7 = 0.f;
    float se0 = 0.f, se1 = 0.f, se2 = 0.f, se3 = 0.f;
    const __half* WhBase = g_Whh + dimBase;

    for (int base = beg; base < end; base += 32) {
        int cnt = end - base; if (cnt > 32) cnt = 32;
        int sv = 0;
        float4 elv = make_float4(0.f, 0.f, 0.f, 0.f);
        if (lane < cnt) {
            sv = g_csrc[base + lane];
            elv = *(const float4*)(g_el + sv * NH);
        }
        float e0 = __expf(lrelu(elv.x + er4.x));
        float e1 = __expf(lrelu(elv.y + er4.y));
        float e2 = __expf(lrelu(elv.z + er4.z));
        float e3 = __expf(lrelu(elv.w + er4.w));
        if (lane >= cnt) { e0 = e1 = e2 = e3 = 0.f; }
        se0 += e0; se1 += e1; se2 += e2; se3 += e3;
        __syncwarp();
        *(float4*)&exsw[lane * 4] = make_float4(e0, e1, e2, e3);
        __syncwarp();
#pragma unroll 8
        for (int j = 0; j < cnt; j += 2) {
            int e = j + hw;
            int ec = (e < cnt) ? e : (cnt - 1);
            int s = __shfl_sync(0xFFFFFFFFu, sv, ec);
            float exh = (e < cnt) ? exsw[e * 4 + myh8] : 0.f;
            uint4 u = *(const uint4*)(WhBase + (size_t)s * DHID);
            float2 f0 = __half22float2(*(__half2*)&u.x);
            float2 f1 = __half22float2(*(__half2*)&u.y);
            float2 f2 = __half22float2(*(__half2*)&u.z);
            float2 f3 = __half22float2(*(__half2*)&u.w);
            a0 = fmaf(exh, f0.x, a0); a1 = fmaf(exh, f0.y, a1);
            a2 = fmaf(exh, f1.x, a2); a3 = fmaf(exh, f1.y, a3);
            a4 = fmaf(exh, f2.x, a4); a5 = fmaf(exh, f2.y, a5);
            a6 = fmaf(exh, f3.x, a6); a7 = fmaf(exh, f3.y, a7);
        }
    }

    // merge half-warps (lane l and l+16 hold same dims, different edge subsets)
    a0 += __shfl_xor_sync(0xFFFFFFFFu, a0, 16);
    a1 += __shfl_xor_sync(0xFFFFFFFFu, a1, 16);
    a2 += __shfl_xor_sync(0xFFFFFFFFu, a2, 16);
    a3 += __shfl_xor_sync(0xFFFFFFFFu, a3, 16);
    a4 += __shfl_xor_sync(0xFFFFFFFFu, a4, 16);
    a5 += __shfl_xor_sync(0xFFFFFFFFu, a5, 16);
    a6 += __shfl_xor_sync(0xFFFFFFFFu, a6, 16);
    a7 += __shfl_xor_sync(0xFFFFFFFFu, a7, 16);

    // full-warp denominator reduction
#pragma unroll
    for (int o = 16; o > 0; o >>= 1) {
        se0 += __shfl_xor_sync(0xFFFFFFFFu, se0, o);
        se1 += __shfl_xor_sync(0xFFFFFFFFu, se1, o);
        se2 += __shfl_xor_sync(0xFFFFFFFFu, se2, o);
        se3 += __shfl_xor_sync(0xFFFFFFFFu, se3, o);
    }
    float seh = (myh8 == 0) ? se0 : (myh8 == 1) ? se1 : (myh8 == 2) ? se2 : se3;
    float r = 1.0f / (seh + EPSV);

    float v0 = a0 * r, v1 = a1 * r, v2 = a2 * r, v3 = a3 * r;
    float v4 = a4 * r, v5 = a5 * r, v6 = a6 * r, v7 = a7 * r;
    v0 += bias[dimBase + 0]; v1 += bias[dimBase + 1];
    v2 += bias[dimBase + 2]; v3 += bias[dimBase + 3];
    v4 += bias[dimBase + 4]; v5 += bias[dimBase + 5];
    v6 += bias[dimBase + 6]; v7 += bias[dimBase + 7];

    if (LAYER == 1) {
        if (hw == 0) {
            float4 w0, w1;
            w0.x = v0 > 0.f ? v0 : (__expf(v0) - 1.0f);
            w0.y = v1 > 0.f ? v1 : (__expf(v1) - 1.0f);
            w0.z = v2 > 0.f ? v2 : (__expf(v2) - 1.0f);
            w0.w = v3 > 0.f ? v3 : (__expf(v3) - 1.0f);
            w1.x = v4 > 0.f ? v4 : (__expf(v4) - 1.0f);
            w1.y = v5 > 0.f ? v5 : (__expf(v5) - 1.0f);
            w1.z = v6 > 0.f ? v6 : (__expf(v6) - 1.0f);
            w1.w = v7 > 0.f ? v7 : (__expf(v7) - 1.0f);
            float* dst = g_z + (size_t)n * DHID + dimBase;
            *(float4*)dst = w0;
            *(float4*)(dst + 4) = w1;
        }
    } else {
        // head mean: sum lanes whose l16 differ in bits 2,3 (same local dim block)
#pragma unroll
        for (int o = 4; o <= 8; o <<= 1) {
            v0 += __shfl_xor_sync(0xFFFFFFFFu, v0, o);
            v1 += __shfl_xor_sync(0xFFFFFFFFu, v1, o);
            v2 += __shfl_xor_sync(0xFFFFFFFFu, v2, o);
            v3 += __shfl_xor_sync(0xFFFFFFFFu, v3, o);
            v4 += __shfl_xor_sync(0xFFFFFFFFu, v4, o);
            v5 += __shfl_xor_sync(0xFFFFFFFFu, v5, o);
            v6 += __shfl_xor_sync(0xFFFFFFFFu, v6, o);
            v7 += __shfl_xor_sync(0xFFFFFFFFu, v7, o);
        }
        if (lane < 4) {
            float4 w0 = make_float4(0.25f * v0, 0.25f * v1, 0.25f * v2, 0.25f * v3);
            float4 w1 = make_float4(0.25f * v4, 0.25f * v5, 0.25f * v6, 0.25f * v7);
            float* dst = g_z2 + (size_t)n * DHEAD + lane * 8;
            *(float4*)dst = w0;
            *(float4*)(dst + 4) = w1;
        }
    }
}

// ================= launch =================
extern "C" void kernel_launch(void* const* d_in, const int* in_sizes, int n_in,
                              void* d_out, int out_size) {
    const float* h   = (const float*)d_in[0];
    const int*   src = (const int*)d_in[1];
    const int*   dst = (const int*)d_in[2];
    const float* W1  = (const float*)d_in[3];
    const float* al1 = (const float*)d_in[4];
    const float* ar1 = (const float*)d_in[5];
    const float* b1  = (const float*)d_in[6];
    const float* W2  = (const float*)d_in[7];
    const float* al2 = (const float*)d_in[8];
    const float* ar2 = (const float*)d_in[9];
    const float* b2  = (const float*)d_in[10];
    const float* Wp  = (const float*)d_in[11];
    const float* bp  = (const float*)d_in[12];
    float* out = (float*)d_out;

    float *p_z, *p_z2;
    int *p_cnt;
    cudaGetSymbolAddress((void**)&p_z,   g_z);
    cudaGetSymbolAddress((void**)&p_z2,  g_z2);
    cudaGetSymbolAddress((void**)&p_cnt, g_cnt);

    const int TPB = 256;
    int gEdge4 = (NE / 4 + TPB - 1) / TPB;
    int gAgg   = (NN + 7) / 8;

    dim3 gemmGrid1(1, (NN + 63) / 64);              // N=128
    dim3 gemmGridP(OUTD / 128, (NN + 63) / 64);     // N=512

    // ---- fork: CSR build on side stream, GEMM1 on main stream ----
    cudaEventRecord(g_evFork, 0);
    cudaStreamWaitEvent(g_s2, g_evFork, 0);
    cudaMemsetAsync(p_cnt, 0, NN * sizeof(int), g_s2);
    k_count<<<gEdge4, TPB, 0, g_s2>>>((const int4*)dst);
    k_scan<<<1, 1024, 0, g_s2>>>();
    k_fill<<<gEdge4, TPB, 0, g_s2>>>((const int4*)src, (const int4*)dst);
    cudaEventRecord(g_evCsr, g_s2);

    // ===== layer 1 =====
    gemm_tc<1><<<gemmGrid1, 256, SMEM_BYTES>>>(h, W1, nullptr, nullptr, NN, DHID, DHID, al1, ar1);
    cudaStreamWaitEvent(0, g_evCsr, 0);   // join: agg needs CSR
    k_gat_agg<1><<<gAgg, 256>>>(b1);

    // ===== layer 2 =====
    gemm_tc<1><<<gemmGrid1, 256, SMEM_BYTES>>>(p_z, W2, nullptr, nullptr, NN, DHID, DHID, al2, ar2);
    k_gat_agg<2><<<gAgg, 256>>>(b2);

    // ===== projection head =====
    gemm_tc<0><<<gemmGridP, 256, SMEM_BYTES>>>(p_z2, Wp, bp, out, NN, OUTD, DHEAD, nullptr, nullptr);
}

// round 10
// speedup vs baseline: 1.2017x; 1.2017x over previous
#include <cuda_runtime.h>
#include <cuda_fp16.h>
#include <math.h>
#include <stdint.h>

#define NN 50000
#define NE 800000
#define DHID 128
#define NH 4
#define DHEAD 32
#define OUTD 512
#define NEG_SLOPE 0.2f
#define EPSV 1e-9f

// GEMM smem layout (floats): 3 stages A[64][20] + 3 stages B[16][132]
#define A_STRIDE 20
#define B_STRIDE 132
#define A_STAGE (64 * A_STRIDE)           // 1280
#define B_STAGE (16 * B_STRIDE)           // 2112
#define SMEM_FLOATS (3 * A_STAGE + 3 * B_STAGE)
#define SMEM_BYTES (SMEM_FLOATS * 4)      // 40704

// ---------------- scratch (device globals; no allocation) ----------------
__device__ __half g_Whh[NN * DHID];   // fp16 message payload
__device__ float g_z[NN * DHID];
__device__ float g_el[NN * NH];
__device__ float g_er[NN * NH];
__device__ float g_z2[NN * DHEAD];
__device__ int   g_cnt[NN];
__device__ int   g_rowptr[NN + 1];
__device__ int   g_epos[NE];
__device__ int   g_csrc[NE];

__device__ __forceinline__ float lrelu(float x) {
    return x > 0.0f ? x : NEG_SLOPE * x;
}

__device__ __forceinline__ uint32_t f2tf32(float x) {
    uint32_t u;
    asm("cvt.rna.tf32.f32 %0, %1;" : "=r"(u) : "f"(x));
    return u;
}

__device__ __forceinline__ void mma_tf32(float* c, const uint32_t* a, const uint32_t* b) {
    asm volatile(
        "mma.sync.aligned.m16n8k8.row.col.f32.tf32.tf32.f32 "
        "{%0,%1,%2,%3}, {%4,%5,%6,%7}, {%8,%9}, {%0,%1,%2,%3};"
        : "+f"(c[0]), "+f"(c[1]), "+f"(c[2]), "+f"(c[3])
        : "r"(a[0]), "r"(a[1]), "r"(a[2]), "r"(a[3]), "r"(b[0]), "r"(b[1]));
}

__device__ __forceinline__ uint32_t su(const void* p) {
    return (uint32_t)__cvta_generic_to_shared(p);
}

__device__ __forceinline__ void cp16(uint32_t dst, const void* src, bool p) {
    int sz = p ? 16 : 0;
    asm volatile("cp.async.cg.shared.global [%0], [%1], 16, %2;"
                 :: "r"(dst), "l"(src), "r"(sz));
}

// ================= tensor-core GEMM (tf32 mma.sync) =================
// Block tile 64x128, 8 warps (2m x 4n) of 32x32 warp tiles, 3-stage cp.async.
// FUSE=1: writes fp16 g_Whh + g_el/g_er (grid.x must be 1, N==128); no fp32 C.
// FUSE=0: writes fp32 C (+bias).  Requires K % 16 == 0, K >= 32, N % 128 == 0.
template <int FUSE>
__global__ void __launch_bounds__(256, 3)
gemm_tc(const float* __restrict__ A, const float* __restrict__ B,
        const float* __restrict__ bias, float* __restrict__ C,
        int M, int N, int K,
        const float* __restrict__ al, const float* __restrict__ ar) {
    extern __shared__ float smem[];

    const int tid = threadIdx.x;
    const int wid = tid >> 5, lane = tid & 31;
    const int g = lane >> 2, t = lane & 3;
    const int wm = wid & 1;               // 2 warp rows x 32
    const int wn = wid >> 1;              // 4 warp cols x 32
    const int rowBase = blockIdx.y * 64;
    const int colBase = blockIdx.x * 128;

    const int aRow = tid >> 2, aK0 = (tid & 3) * 4;
    const int bK0 = tid >> 5, bN0 = (tid & 31) * 4;
    const bool ap = (rowBase + aRow) < M;
    const float* aSrc = A + (size_t)(ap ? rowBase + aRow : 0) * K + aK0;
    const float* bSrc0 = B + (size_t)bK0 * N + colBase + bN0;
    const float* bSrc1 = B + (size_t)(bK0 + 8) * N + colBase + bN0;

    float acc[2][4][4];
#pragma unroll
    for (int mf = 0; mf < 2; mf++)
#pragma unroll
        for (int nf = 0; nf < 4; nf++)
#pragma unroll
            for (int r = 0; r < 4; r++) acc[mf][nf][r] = 0.0f;

    const int nStages = K >> 4;

    uint32_t aDst = su(smem + aRow * A_STRIDE + aK0);
    uint32_t bDst0 = su(smem + 3 * A_STAGE + bK0 * B_STRIDE + bN0);
    uint32_t bDst1 = su(smem + 3 * A_STAGE + (bK0 + 8) * B_STRIDE + bN0);

#pragma unroll
    for (int s = 0; s < 2; s++) {
        int k0g = s * 16;
        cp16(aDst + s * A_STAGE * 4, aSrc + k0g, ap);
        cp16(bDst0 + s * B_STAGE * 4, bSrc0 + (size_t)k0g * N, true);
        cp16(bDst1 + s * B_STAGE * 4, bSrc1 + (size_t)k0g * N, true);
        asm volatile("cp.async.commit_group;");
    }

    for (int st = 0; st < nStages; st++) {
        if (nStages - st >= 2) asm volatile("cp.async.wait_group 1;" ::: "memory");
        else                   asm volatile("cp.async.wait_group 0;" ::: "memory");
        __syncthreads();

        const int cur = st % 3;
        const float* Asf = smem + cur * A_STAGE;
        const float* Bsf = smem + 3 * A_STAGE + cur * B_STAGE;

#pragma unroll
        for (int kk = 0; kk < 2; kk++) {
            const int k0 = kk * 8;
            uint32_t af[2][4], bf[4][2];
#pragma unroll
            for (int mf = 0; mf < 2; mf++) {
                int r0 = wm * 32 + mf * 16 + g;
                af[mf][0] = f2tf32(Asf[r0 * A_STRIDE + k0 + t]);
                af[mf][1] = f2tf32(Asf[(r0 + 8) * A_STRIDE + k0 + t]);
                af[mf][2] = f2tf32(Asf[r0 * A_STRIDE + k0 + t + 4]);
                af[mf][3] = f2tf32(Asf[(r0 + 8) * A_STRIDE + k0 + t + 4]);
            }
#pragma unroll
            for (int nf = 0; nf < 4; nf++) {
                int n0 = wn * 32 + nf * 8 + g;
                bf[nf][0] = f2tf32(Bsf[(k0 + t) * B_STRIDE + n0]);
                bf[nf][1] = f2tf32(Bsf[(k0 + t + 4) * B_STRIDE + n0]);
            }
#pragma unroll
            for (int mf = 0; mf < 2; mf++)
#pragma unroll
                for (int nf = 0; nf < 4; nf++)
                    mma_tf32(acc[mf][nf], af[mf], bf[nf]);
        }

        if (st + 2 < nStages) {
            int s = (st + 2) % 3;
            int k0g = (st + 2) * 16;
            cp16(aDst + s * A_STAGE * 4, aSrc + k0g, ap);
            cp16(bDst0 + s * B_STAGE * 4, bSrc0 + (size_t)k0g * N, true);
            cp16(bDst1 + s * B_STAGE * 4, bSrc1 + (size_t)k0g * N, true);
            asm volatile("cp.async.commit_group;");
        }
    }

    if (!FUSE) {
#pragma unroll
        for (int mf = 0; mf < 2; mf++) {
            int row0 = rowBase + wm * 32 + mf * 16 + g;
#pragma unroll
            for (int nf = 0; nf < 4; nf++) {
                int col = colBase + wn * 32 + nf * 8 + 2 * t;
                float b0 = bias ? bias[col] : 0.f;
                float b1 = bias ? bias[col + 1] : 0.f;
                if (row0 < M) {
                    float2 v = make_float2(acc[mf][nf][0] + b0, acc[mf][nf][1] + b1);
                    *(float2*)(C + (size_t)row0 * N + col) = v;
                }
                if (row0 + 8 < M) {
                    float2 v = make_float2(acc[mf][nf][2] + b0, acc[mf][nf][3] + b1);
                    *(float2*)(C + (size_t)(row0 + 8) * N + col) = v;
                }
            }
        }
    } else {
        float elp[2][2] = {}, erp[2][2] = {};   // [mf][rh]
#pragma unroll
        for (int nf = 0; nf < 4; nf++) {
            int col = wn * 32 + nf * 8 + 2 * t;
            float la0 = al[col], la1 = al[col + 1];
            float ra0 = ar[col], ra1 = ar[col + 1];
#pragma unroll
            for (int mf = 0; mf < 2; mf++) {
                elp[mf][0] += acc[mf][nf][0] * la0 + acc[mf][nf][1] * la1;
                elp[mf][1] += acc[mf][nf][2] * la0 + acc[mf][nf][3] * la1;
                erp[mf][0] += acc[mf][nf][0] * ra0 + acc[mf][nf][1] * ra1;
                erp[mf][1] += acc[mf][nf][2] * ra0 + acc[mf][nf][3] * ra1;
                int row0 = rowBase + wm * 32 + mf * 16 + g;
                if (row0 < M) {
                    __half2 hv = __floats2half2_rn(acc[mf][nf][0], acc[mf][nf][1]);
                    *(__half2*)(g_Whh + (size_t)row0 * DHID + col) = hv;
                }
                if (row0 + 8 < M) {
                    __half2 hv = __floats2half2_rn(acc[mf][nf][2], acc[mf][nf][3]);
                    *(__half2*)(g_Whh + (size_t)(row0 + 8) * DHID + col) = hv;
                }
            }
        }
#pragma unroll
        for (int mf = 0; mf < 2; mf++)
#pragma unroll
            for (int rh = 0; rh < 2; rh++) {
                float v = elp[mf][rh];
                v += __shfl_xor_sync(0xFFFFFFFFu, v, 1);
                v += __shfl_xor_sync(0xFFFFFFFFu, v, 2);
                elp[mf][rh] = v;
                float w = erp[mf][rh];
                w += __shfl_xor_sync(0xFFFFFFFFu, w, 1);
                w += __shfl_xor_sync(0xFFFFFFFFu, w, 2);
                erp[mf][rh] = w;
            }
        if (t == 0) {
#pragma unroll
            for (int mf = 0; mf < 2; mf++)
#pragma unroll
                for (int rh = 0; rh < 2; rh++) {
                    int gr = rowBase + wm * 32 + mf * 16 + g + rh * 8;
                    if (gr < M) {
                        g_el[gr * NH + wn] = elp[mf][rh];
                        g_er[gr * NH + wn] = erp[mf][rh];
                    }
                }
        }
    }
}

// ---------------- streams/events for fork-join + func attrs ----------------
static cudaStream_t g_s2;
static cudaEvent_t g_evFork, g_evCsr;
struct HostInit {
    HostInit() {
        cudaStreamCreateWithFlags(&g_s2, cudaStreamNonBlocking);
        cudaEventCreateWithFlags(&g_evFork, cudaEventDisableTiming);
        cudaEventCreateWithFlags(&g_evCsr, cudaEventDisableTiming);
        cudaFuncSetAttribute(gemm_tc<0>, cudaFuncAttributeMaxDynamicSharedMemorySize, SMEM_BYTES);
        cudaFuncSetAttribute(gemm_tc<1>, cudaFuncAttributeMaxDynamicSharedMemorySize, SMEM_BYTES);
    }
};
static HostInit g_hostInit;

// ================= CSR build (int4-vectorized, epos-based) =================
__global__ void k_count(const int4* __restrict__ dst4) {
    int i = blockIdx.x * blockDim.x + threadIdx.x;
    if (i >= NE / 4) return;
    int4 d = dst4[i];
    int4 p;
    p.x = atomicAdd(&g_cnt[d.x], 1);
    p.y = atomicAdd(&g_cnt[d.y], 1);
    p.z = atomicAdd(&g_cnt[d.z], 1);
    p.w = atomicAdd(&g_cnt[d.w], 1);
    ((int4*)g_epos)[i] = p;
}

__global__ void k_scan() {
    __shared__ int warpsum[32];
    const int T = 1024;
    const int CH = (NN + T - 1) / T;
    int t = threadIdx.x;
    int lane = t & 31, wid = t >> 5;
    int lo = t * CH;
    int hi = lo + CH; if (hi > NN) hi = NN;
    if (lo > NN) lo = NN;
    int s = 0;
    for (int i = lo; i < hi; i++) s += g_cnt[i];
    int v = s;
#pragma unroll
    for (int o = 1; o < 32; o <<= 1) {
        int u = __shfl_up_sync(0xFFFFFFFFu, v, o);
        if (lane >= o) v += u;
    }
    if (lane == 31) warpsum[wid] = v;
    __syncthreads();
    if (wid == 0) {
        int w = warpsum[lane];
#pragma unroll
        for (int o = 1; o < 32; o <<= 1) {
            int u = __shfl_up_sync(0xFFFFFFFFu, w, o);
            if (lane >= o) w += u;
        }
        warpsum[lane] = w;
    }
    __syncthreads();
    int excl = v - s + (wid > 0 ? warpsum[wid - 1] : 0);
    int run = excl;
    for (int i = lo; i < hi; i++) {
        g_rowptr[i] = run;
        run += g_cnt[i];
    }
    if (t == T - 1) g_rowptr[NN] = run;
}

__global__ void k_fill(const int4* __restrict__ src4, const int4* __restrict__ dst4) {
    int i = blockIdx.x * blockDim.x + threadIdx.x;
    if (i >= NE / 4) return;
    int4 s = src4[i];
    int4 d = dst4[i];
    int4 p = ((const int4*)g_epos)[i];
    g_csrc[g_rowptr[d.x] + p.x] = s.x;
    g_csrc[g_rowptr[d.y] + p.y] = s.y;
    g_csrc[g_rowptr[d.z] + p.z] = s.z;
    g_csrc[g_rowptr[d.w] + p.w] = s.w;
}

// ================= fused softmax + aggregate (warp per node, smem exp stage) ====
// 512 threads = 16 nodes per block.
template <int LAYER>
__global__ void k_gat_agg(const float* __restrict__ bias) {
    __shared__ float exsAll[16][128];
    int wIn = threadIdx.x >> 5;
    int n = (blockIdx.x << 4) + wIn;
    if (n >= NN) return;
    float* exsw = exsAll[wIn];
    int lane = threadIdx.x & 31;
    int myh = lane >> 3;
    int beg = g_rowptr[n], end = g_rowptr[n + 1];
    float4 er4 = *(const float4*)(g_er + n * NH);

    float ax = 0.f, ay = 0.f, az = 0.f, aw = 0.f;
    float se0 = 0.f, se1 = 0.f, se2 = 0.f, se3 = 0.f;
    const __half* WhBase = g_Whh + (size_t)(lane * 4);

    for (int base = beg; base < end; base += 32) {
        int cnt = end - base; if (cnt > 32) cnt = 32;
        int sv = 0;
        float4 elv = make_float4(0.f, 0.f, 0.f, 0.f);
        if (lane < cnt) {
            sv = g_csrc[base + lane];
            elv = *(const float4*)(g_el + sv * NH);
        }
        float e0 = __expf(lrelu(elv.x + er4.x));
        float e1 = __expf(lrelu(elv.y + er4.y));
        float e2 = __expf(lrelu(elv.z + er4.z));
        float e3 = __expf(lrelu(elv.w + er4.w));
        if (lane >= cnt) { e0 = e1 = e2 = e3 = 0.f; }
        se0 += e0; se1 += e1; se2 += e2; se3 += e3;
        __syncwarp();
        *(float4*)&exsw[lane * 4] = make_float4(e0, e1, e2, e3);
        __syncwarp();
#pragma unroll 16
        for (int j = 0; j < cnt; j++) {
            int s = __shfl_sync(0xFFFFFFFFu, sv, j);
            float exh = exsw[j * 4 + myh];
            uint2 u = *(const uint2*)(WhBase + (size_t)s * DHID);
            float2 f0 = __half22float2(*(__half2*)&u.x);
            float2 f1 = __half22float2(*(__half2*)&u.y);
            ax = fmaf(exh, f0.x, ax);
            ay = fmaf(exh, f0.y, ay);
            az = fmaf(exh, f1.x, az);
            aw = fmaf(exh, f1.y, aw);
        }
    }
#pragma unroll
    for (int o = 16; o > 0; o >>= 1) {
        se0 += __shfl_xor_sync(0xFFFFFFFFu, se0, o);
        se1 += __shfl_xor_sync(0xFFFFFFFFu, se1, o);
        se2 += __shfl_xor_sync(0xFFFFFFFFu, se2, o);
        se3 += __shfl_xor_sync(0xFFFFFFFFu, se3, o);
    }
    float seh = myh < 2 ? (myh == 0 ? se0 : se1) : (myh == 2 ? se2 : se3);
    float r = 1.0f / (seh + EPSV);
    ax *= r; ay *= r; az *= r; aw *= r;

    if (LAYER == 1) {
        int d = lane * 4;
        float4 v;
        v.x = ax + bias[d + 0];
        v.y = ay + bias[d + 1];
        v.z = az + bias[d + 2];
        v.w = aw + bias[d + 3];
        v.x = v.x > 0.f ? v.x : (__expf(v.x) - 1.0f);
        v.y = v.y > 0.f ? v.y : (__expf(v.y) - 1.0f);
        v.z = v.z > 0.f ? v.z : (__expf(v.z) - 1.0f);
        v.w = v.w > 0.f ? v.w : (__expf(v.w) - 1.0f);
        *(float4*)(g_z + (size_t)n * DHID + d) = v;
    } else {
        int d = lane * 4;
        ax += bias[d + 0]; ay += bias[d + 1]; az += bias[d + 2]; aw += bias[d + 3];
#pragma unroll
        for (int o = 8; o <= 16; o <<= 1) {
            ax += __shfl_xor_sync(0xFFFFFFFFu, ax, o);
            ay += __shfl_xor_sync(0xFFFFFFFFu, ay, o);
            az += __shfl_xor_sync(0xFFFFFFFFu, az, o);
            aw += __shfl_xor_sync(0xFFFFFFFFu, aw, o);
        }
        if (lane < 8) {
            float4 v = make_float4(0.25f * ax, 0.25f * ay, 0.25f * az, 0.25f * aw);
            *(float4*)(g_z2 + (size_t)n * DHEAD + lane * 4) = v;
        }
    }
}

// ================= launch =================
extern "C" void kernel_launch(void* const* d_in, const int* in_sizes, int n_in,
                              void* d_out, int out_size) {
    const float* h   = (const float*)d_in[0];
    const int*   src = (const int*)d_in[1];
    const int*   dst = (const int*)d_in[2];
    const float* W1  = (const float*)d_in[3];
    const float* al1 = (const float*)d_in[4];
    const float* ar1 = (const float*)d_in[5];
    const float* b1  = (const float*)d_in[6];
    const float* W2  = (const float*)d_in[7];
    const float* al2 = (const float*)d_in[8];
    const float* ar2 = (const float*)d_in[9];
    const float* b2  = (const float*)d_in[10];
    const float* Wp  = (const float*)d_in[11];
    const float* bp  = (const float*)d_in[12];
    float* out = (float*)d_out;

    float *p_z, *p_z2;
    int *p_cnt;
    cudaGetSymbolAddress((void**)&p_z,   g_z);
    cudaGetSymbolAddress((void**)&p_z2,  g_z2);
    cudaGetSymbolAddress((void**)&p_cnt, g_cnt);

    const int TPB = 256;
    int gEdge4 = (NE / 4 + TPB - 1) / TPB;
    int gAgg   = (NN + 15) / 16;

    dim3 gemmGrid1(1, (NN + 63) / 64);              // N=128
    dim3 gemmGridP(OUTD / 128, (NN + 63) / 64);     // N=512

    // ---- fork: CSR build on side stream, GEMM1 on main stream ----
    cudaEventRecord(g_evFork, 0);
    cudaStreamWaitEvent(g_s2, g_evFork, 0);
    cudaMemsetAsync(p_cnt, 0, NN * sizeof(int), g_s2);
    k_count<<<gEdge4, TPB, 0, g_s2>>>((const int4*)dst);
    k_scan<<<1, 1024, 0, g_s2>>>();
    k_fill<<<gEdge4, TPB, 0, g_s2>>>((const int4*)src, (const int4*)dst);
    cudaEventRecord(g_evCsr, g_s2);

    // ===== layer 1 =====
    gemm_tc<1><<<gemmGrid1, 256, SMEM_BYTES>>>(h, W1, nullptr, nullptr, NN, DHID, DHID, al1, ar1);
    cudaStreamWaitEvent(0, g_evCsr, 0);   // join: agg needs CSR
    k_gat_agg<1><<<gAgg, 512>>>(b1);

    // ===== layer 2 =====
    gemm_tc<1><<<gemmGrid1, 256, SMEM_BYTES>>>(p_z, W2, nullptr, nullptr, NN, DHID, DHID, al2, ar2);
    k_gat_agg<2><<<gAgg, 512>>>(b2);

    // ===== projection head =====
    gemm_tc<0><<<gemmGridP, 256, SMEM_BYTES>>>(p_z2, Wp, bp, out, NN, OUTD, DHEAD, nullptr, nullptr);
}